// round 9
// baseline (speedup 1.0000x reference)
#include <cuda_runtime.h>
#include <cuda_bf16.h>
#include <cstdint>
#include <math.h>

// Problem dims (fixed per reference)
#define NROWS 16384
#define IND   512
#define HIDD  256
#define OD    128
#define NB    (NROWS / 128)

// Scratch (device globals; no allocations allowed)
__device__ __nv_bfloat16 g_xb [NROWS * IND];    // bf16 x
__device__ __nv_bfloat16 g_w1b[IND * HIDD];     // bf16 W1
__device__ __nv_bfloat16 g_w2b[HIDD * OD];      // bf16 W2
__device__ __nv_bfloat16 g_h1b[NROWS * HIDD];   // bf16 h1 (after leaky)
__device__ float         g_h  [NROWS * OD];     // fp32 h (epilogue)
__device__ __nv_bfloat16 g_hb [NROWS * OD];     // bf16 h  [N][128]
__device__ __nv_bfloat16 g_hbT[OD * NROWS];     // bf16 h^T [128][N]

// ===========================================================================
// PTX helpers (sm_80+ baseline only)
// ===========================================================================
__device__ __forceinline__ uint32_t smem_to_u32(const void* p) {
    uint32_t a;
    asm("{ .reg .u64 t; cvta.to.shared.u64 t, %1; cvt.u32.u64 %0, t; }"
        : "=r"(a) : "l"(p));
    return a;
}

__device__ __forceinline__ void cp_async16(uint32_t dst, const void* src) {
    asm volatile("cp.async.cg.shared.global [%0], [%1], 16;"
                 :: "r"(dst), "l"(src));
}
#define CP_COMMIT asm volatile("cp.async.commit_group;" ::: "memory")
#define CP_WAIT0  asm volatile("cp.async.wait_group 0;" ::: "memory")

__device__ __forceinline__ void ldsm_x4(uint32_t* r, uint32_t addr) {
    asm volatile("ldmatrix.sync.aligned.m8n8.x4.shared.b16 {%0,%1,%2,%3}, [%4];"
                 : "=r"(r[0]), "=r"(r[1]), "=r"(r[2]), "=r"(r[3]) : "r"(addr));
}
__device__ __forceinline__ void ldsm_x4_t(uint32_t* r, uint32_t addr) {
    asm volatile("ldmatrix.sync.aligned.m8n8.x4.trans.shared.b16 {%0,%1,%2,%3}, [%4];"
                 : "=r"(r[0]), "=r"(r[1]), "=r"(r[2]), "=r"(r[3]) : "r"(addr));
}

// D += A@B, m16n8k16, bf16 in, fp32 acc
__device__ __forceinline__ void mma16816(float* c, const uint32_t* a,
                                         const uint32_t b0, const uint32_t b1) {
    asm volatile(
        "mma.sync.aligned.m16n8k16.row.col.f32.bf16.bf16.f32 "
        "{%0,%1,%2,%3}, {%4,%5,%6,%7}, {%8,%9}, {%0,%1,%2,%3};"
        : "+f"(c[0]), "+f"(c[1]), "+f"(c[2]), "+f"(c[3])
        : "r"(a[0]), "r"(a[1]), "r"(a[2]), "r"(a[3]), "r"(b0), "r"(b1));
}

__device__ __forceinline__ uint32_t pack_bf16x2(float hi, float lo) {
    uint32_t d;
    asm("cvt.rn.bf16x2.f32 %0, %1, %2;" : "=r"(d) : "f"(hi), "f"(lo));
    return d;
}
__device__ __forceinline__ uint32_t hmul2(uint32_t a, uint32_t b) {
    uint32_t d;
    asm("mul.rn.bf16x2 %0, %1, %2;" : "=r"(d) : "r"(a), "r"(b));
    return d;
}
__device__ __forceinline__ float ex2f(float x) {
    float d;
    asm("ex2.approx.f32 %0, %1;" : "=f"(d) : "f"(x));
    return d;
}
#define L2E_BF16X2 0x3FB93FB9u   // bf16x2 {log2(e), log2(e)}

// ===========================================================================
// fp32 -> bf16 conversion (vectorized x4)
// ===========================================================================
__global__ __launch_bounds__(256) void cvt_bf16_kernel(
    const float* __restrict__ in, __nv_bfloat16* __restrict__ out, int n4)
{
    int i = blockIdx.x * 256 + threadIdx.x;
    if (i < n4) {
        float4 v = ((const float4*)in)[i];
        ((uint2*)out)[i] = make_uint2(pack_bf16x2(v.y, v.x),
                                      pack_bf16x2(v.w, v.z));
    }
}

// ===========================================================================
// transpose: g_hb [N][128] -> g_hbT [128][N]   (bf16, one-time, ~8MB traffic)
// ===========================================================================
__global__ __launch_bounds__(256) void transpose_kernel(
    const __nv_bfloat16* __restrict__ hb, __nv_bfloat16* __restrict__ hbT)
{
    __shared__ __nv_bfloat16 tile[64][130];
    const int r0 = blockIdx.x * 64;
    const int tid = threadIdx.x;

    for (int idx = tid; idx < 64 * 128; idx += 256) {
        int r = idx >> 7, c = idx & 127;
        tile[r][c] = hb[(size_t)(r0 + r) * OD + c];
    }
    __syncthreads();

    const int rr = tid & 63;
    const int cb = tid >> 6;
    #pragma unroll
    for (int cc = 0; cc < 128; cc += 4) {
        int c = cc + cb;
        hbT[(size_t)c * NROWS + r0 + rr] = tile[rr][c];
    }
}

// ===========================================================================
// bf16 HMMA GEMM: C = A(bf16)@B(bf16) + bias, optional LeakyReLU.
// ===========================================================================
#define GA_STRIDE 144
#define GA_BUF    (128 * GA_STRIDE)
#define GB_STRIDE 272
#define GB_BUF    (64 * GB_STRIDE)
#define GEMM_SMEM (2 * GA_BUF + 2 * GB_BUF)

template<int KDIM, int NGLOB, bool LEAKY, bool WRITE_F32>
__global__ __launch_bounds__(256, 2) void hgemm_kernel(
    const __nv_bfloat16* __restrict__ A, const __nv_bfloat16* __restrict__ B,
    const float* __restrict__ bias, float* __restrict__ C,
    __nv_bfloat16* __restrict__ Cb)
{
    extern __shared__ char smem[];
    const uint32_t sb = smem_to_u32(smem);
    const int tid = threadIdx.x;
    const int wid = tid >> 5, lane = tid & 31;
    const int m0 = blockIdx.y * 128, n0 = blockIdx.x * 128;

    const uint32_t sA[2] = { sb, sb + GA_BUF };
    const uint32_t sB[2] = { sb + 2 * GA_BUF, sb + 2 * GA_BUF + GB_BUF };

    float acc[16][4];
    #pragma unroll
    for (int i = 0; i < 16; i++)
        #pragma unroll
        for (int j = 0; j < 4; j++) acc[i][j] = 0.f;

    const int brow  = lane & 15;
    const int bcolb = ((lane >> 4) << 3) * 2;
    const int vrow  = ((lane >> 4) << 3) + (lane & 7);
    const int vcolb = (((lane >> 3) & 1) << 3) * 2;

    auto fill = [&](int bi, int k0) {
        #pragma unroll
        for (int it = 0; it < 4; it++) {
            int c = it * 256 + tid;
            int r = c >> 3, c8 = c & 7;
            cp_async16(sA[bi] + r * GA_STRIDE + c8 * 16,
                       A + (size_t)(m0 + r) * KDIM + k0 + c8 * 8);
        }
        #pragma unroll
        for (int it = 0; it < 4; it++) {
            int c = it * 256 + tid;
            int r = c >> 4, cc = c & 15;
            cp_async16(sB[bi] + r * GB_STRIDE + cc * 16,
                       B + (size_t)(k0 + r) * NGLOB + n0 + cc * 8);
        }
        CP_COMMIT;
    };

    fill(0, 0);
    constexpr int NC = KDIM / 64;

    for (int ck = 0; ck < NC; ck++) {
        CP_WAIT0;
        __syncthreads();
        if (ck + 1 < NC) fill((ck + 1) & 1, (ck + 1) * 64);

        const uint32_t cA = sA[ck & 1], cB = sB[ck & 1];

        uint32_t af[4][4];
        const uint32_t ab = cA + (wid * 16 + brow) * GA_STRIDE + bcolb;
        #pragma unroll
        for (int kt = 0; kt < 4; kt++) ldsm_x4(af[kt], ab + kt * 32);

        #pragma unroll
        for (int kt = 0; kt < 4; kt++) {
            const uint32_t rb = cB + (kt * 16 + vrow) * GB_STRIDE + vcolb;
            #pragma unroll
            for (int jp = 0; jp < 8; jp++) {
                uint32_t r[4];
                ldsm_x4_t(r, rb + jp * 32);
                mma16816(acc[2 * jp],     af[kt], r[0], r[2]);
                mma16816(acc[2 * jp + 1], af[kt], r[1], r[3]);
            }
        }
    }

    const int g = lane >> 2, t = lane & 3;
    const int row_lo = m0 + wid * 16 + g;
    const int row_hi = row_lo + 8;
    #pragma unroll
    for (int nt = 0; nt < 16; nt++) {
        const int col = n0 + nt * 8 + 2 * t;
        const float bb0 = bias[col], bb1 = bias[col + 1];
        float v0 = acc[nt][0] + bb0, v1 = acc[nt][1] + bb1;
        float v2 = acc[nt][2] + bb0, v3 = acc[nt][3] + bb1;
        if (LEAKY) {
            v0 = v0 >= 0.f ? v0 : 0.01f * v0;
            v1 = v1 >= 0.f ? v1 : 0.01f * v1;
            v2 = v2 >= 0.f ? v2 : 0.01f * v2;
            v3 = v3 >= 0.f ? v3 : 0.01f * v3;
        }
        if (WRITE_F32) {
            *(float2*)(C + (size_t)row_lo * NGLOB + col) = make_float2(v0, v1);
            *(float2*)(C + (size_t)row_hi * NGLOB + col) = make_float2(v2, v3);
        }
        *(uint32_t*)(Cb + (size_t)row_lo * NGLOB + col) = pack_bf16x2(v1, v0);
        *(uint32_t*)(Cb + (size_t)row_hi * NGLOB + col) = pack_bf16x2(v3, v2);
    }
}

// ===========================================================================
// HMMA flash similarity kernel (R9):
//   - PV B-fragments via NON-trans ldmatrix on a pre-transposed V^T tile
//     (B-frag of V == A-frag of V^T): zero movmatrix on the tensor pipe.
//   - rv loads are issued before the S-MMA chain -> hidden under it.
//   - Q-frags pre-scaled by log2(e); exp via raw ex2.approx.
//   Math otherwise identical to R4.
// ===========================================================================
#define ROW_BYTES 272
#define TILE_BYTES (128 * ROW_BYTES)          // 34816
#define FLASH_SMEM (4 * TILE_BYTES)           // 139264 (2 buffers x (K + VT))

// 256-thread loaders (no commit; caller commits once per stage)
__device__ __forceinline__ void load_tile(uint32_t dbase,
                                          const __nv_bfloat16* src, int tid) {
    #pragma unroll
    for (int it = 0; it < 8; it++) {
        int c = it * 256 + tid;
        int row = c >> 4, col = c & 15;
        cp_async16(dbase + row * ROW_BYTES + col * 16, src + row * OD + col * 8);
    }
}
__device__ __forceinline__ void load_tileT(uint32_t dbase,
                                           const __nv_bfloat16* hbT, int c0,
                                           int tid) {
    #pragma unroll
    for (int it = 0; it < 8; it++) {
        int c = it * 256 + tid;
        int row = c >> 4, col = c & 15;   // row = d (0..127), col*8 = n offset
        cp_async16(dbase + row * ROW_BYTES + col * 16,
                   hbT + (size_t)row * NROWS + c0 + col * 8);
    }
}

__global__ __launch_bounds__(256, 1)
void flash_hmma_kernel(const __nv_bfloat16* __restrict__ hb,
                       const __nv_bfloat16* __restrict__ hbT,
                       const float* __restrict__ h,
                       const float* __restrict__ alpha,
                       const float* __restrict__ beta,
                       float* __restrict__ out)
{
    extern __shared__ char smem[];
    const uint32_t sbase = smem_to_u32(smem);
    const int tid = threadIdx.x;
    const int wid = tid >> 5, lane = tid & 31;
    const int r0 = blockIdx.x * 128;

    const int brow  = lane & 15;
    const int bcolb = ((lane >> 4) << 3) * 2;

    // ---- Stage Q tile (into buf0 K-slot), capture A-fragments, scale ----
    load_tile(sbase, hb + (size_t)r0 * OD, tid);
    CP_COMMIT; CP_WAIT0;
    __syncthreads();

    uint32_t qf[8][4];
    {
        const uint32_t qb = sbase + (wid * 16 + brow) * ROW_BYTES + bcolb;
        #pragma unroll
        for (int kt = 0; kt < 8; kt++) {
            ldsm_x4(qf[kt], qb + kt * 32);
            #pragma unroll
            for (int i = 0; i < 4; i++)
                qf[kt][i] = hmul2(qf[kt][i], L2E_BF16X2);  // fold log2(e)
        }
    }
    __syncthreads();

    // ---- Prefetch key-block 0 (K tile + V^T tile) into buf0 ----
    load_tile(sbase, hb, tid);
    load_tileT(sbase + TILE_BYTES, hbT, 0, tid);
    CP_COMMIT;

    float oacc[16][4];
    #pragma unroll
    for (int i = 0; i < 16; i++)
        #pragma unroll
        for (int j = 0; j < 4; j++) oacc[i][j] = 0.f;
    float l0 = 0.f, l1 = 0.f;

    for (int kb = 0; kb < NB; kb++) {
        CP_WAIT0;
        __syncthreads();
        if (kb + 1 < NB) {
            const uint32_t nb_base = sbase + (uint32_t)((kb + 1) & 1) * 2 * TILE_BYTES;
            load_tile(nb_base, hb + (size_t)(kb + 1) * 128 * OD, tid);
            load_tileT(nb_base + TILE_BYTES, hbT, (kb + 1) * 128, tid);
            CP_COMMIT;
        }

        const uint32_t curK  = sbase + (uint32_t)(kb & 1) * 2 * TILE_BYTES;
        const uint32_t curVT = curK + TILE_BYTES;

        #pragma unroll
        for (int nbk = 0; nbk < 8; nbk++) {
            // K fragments for S (non-trans; rows = n, cols = d)
            uint32_t r[8][4];
            const uint32_t rb = curK + (nbk * 16 + brow) * ROW_BYTES + bcolb;
            #pragma unroll
            for (int dk = 0; dk < 8; dk++) ldsm_x4(r[dk], rb + dk * 32);

            // V^T fragments for PV (non-trans on [d][n] tile; independent of S,
            // issued now so they hide under the S-MMA chain)
            uint32_t rv[8][4];
            const uint32_t vb = curVT + brow * ROW_BYTES + nbk * 32 + bcolb;
            #pragma unroll
            for (int dk = 0; dk < 8; dk++)
                ldsm_x4(rv[dk], vb + (uint32_t)dk * 16 * ROW_BYTES);

            // S' = (Q*log2e) @ K^T for this n-block
            float s0[4] = {0.f, 0.f, 0.f, 0.f};
            float s1[4] = {0.f, 0.f, 0.f, 0.f};
            #pragma unroll
            for (int dk = 0; dk < 8; dk++) {
                mma16816(s0, qf[dk], r[dk][0], r[dk][2]);
                mma16816(s1, qf[dk], r[dk][1], r[dk][3]);
            }

            // masked exp: p = (s'>0) ? 2^{s'} : 0   (sign test scale-invariant)
            float p00 = s0[0] > 0.f ? ex2f(s0[0]) : 0.f;
            float p01 = s0[1] > 0.f ? ex2f(s0[1]) : 0.f;
            float p02 = s0[2] > 0.f ? ex2f(s0[2]) : 0.f;
            float p03 = s0[3] > 0.f ? ex2f(s0[3]) : 0.f;
            float p10 = s1[0] > 0.f ? ex2f(s1[0]) : 0.f;
            float p11 = s1[1] > 0.f ? ex2f(s1[1]) : 0.f;
            float p12 = s1[2] > 0.f ? ex2f(s1[2]) : 0.f;
            float p13 = s1[3] > 0.f ? ex2f(s1[3]) : 0.f;
            l0 += (p00 + p01) + (p10 + p11);
            l1 += (p02 + p03) + (p12 + p13);
            uint32_t af[4] = { pack_bf16x2(p01, p00), pack_bf16x2(p03, p02),
                               pack_bf16x2(p11, p10), pack_bf16x2(p13, p12) };

            // O += P @ V ; B-frags = A-frag regs of V^T (no transpose needed)
            #pragma unroll
            for (int dk = 0; dk < 8; dk++) {
                mma16816(oacc[2 * dk],     af, rv[dk][0], rv[dk][2]);
                mma16816(oacc[2 * dk + 1], af, rv[dk][1], rv[dk][3]);
            }
        }
    }

    // ---- reduce row sums across the quad ----
    l0 += __shfl_xor_sync(0xffffffffu, l0, 1);
    l0 += __shfl_xor_sync(0xffffffffu, l0, 2);
    l1 += __shfl_xor_sync(0xffffffffu, l1, 1);
    l1 += __shfl_xor_sync(0xffffffffu, l1, 2);

    // ---- epilogue: v = alpha*O/l + beta*h, then log_softmax per row ----
    const float a_ = alpha[0], b_ = beta[0];
    const float s0_ = a_ / l0, s1_ = a_ / l1;
    const int g = lane >> 2, t = lane & 3;
    const int row_lo = r0 + wid * 16 + g;
    const int row_hi = row_lo + 8;

    float mx0 = -INFINITY, mx1 = -INFINITY;
    #pragma unroll
    for (int nt = 0; nt < 16; nt++) {
        const int col = nt * 8 + 2 * t;
        float2 hlo = *(const float2*)(h + (size_t)row_lo * OD + col);
        float2 hhi = *(const float2*)(h + (size_t)row_hi * OD + col);
        float v0 = s0_ * oacc[nt][0] + b_ * hlo.x;
        float v1 = s0_ * oacc[nt][1] + b_ * hlo.y;
        float v2 = s1_ * oacc[nt][2] + b_ * hhi.x;
        float v3 = s1_ * oacc[nt][3] + b_ * hhi.y;
        oacc[nt][0] = v0; oacc[nt][1] = v1;
        oacc[nt][2] = v2; oacc[nt][3] = v3;
        mx0 = fmaxf(mx0, fmaxf(v0, v1));
        mx1 = fmaxf(mx1, fmaxf(v2, v3));
    }
    mx0 = fmaxf(mx0, __shfl_xor_sync(0xffffffffu, mx0, 1));
    mx0 = fmaxf(mx0, __shfl_xor_sync(0xffffffffu, mx0, 2));
    mx1 = fmaxf(mx1, __shfl_xor_sync(0xffffffffu, mx1, 1));
    mx1 = fmaxf(mx1, __shfl_xor_sync(0xffffffffu, mx1, 2));

    float se0 = 0.f, se1 = 0.f;
    #pragma unroll
    for (int nt = 0; nt < 16; nt++) {
        se0 += __expf(oacc[nt][0] - mx0) + __expf(oacc[nt][1] - mx0);
        se1 += __expf(oacc[nt][2] - mx1) + __expf(oacc[nt][3] - mx1);
    }
    se0 += __shfl_xor_sync(0xffffffffu, se0, 1);
    se0 += __shfl_xor_sync(0xffffffffu, se0, 2);
    se1 += __shfl_xor_sync(0xffffffffu, se1, 1);
    se1 += __shfl_xor_sync(0xffffffffu, se1, 2);
    const float lse0 = mx0 + logf(se0);
    const float lse1 = mx1 + logf(se1);

    #pragma unroll
    for (int nt = 0; nt < 16; nt++) {
        const int col = nt * 8 + 2 * t;
        *(float2*)(out + (size_t)row_lo * OD + col) =
            make_float2(oacc[nt][0] - lse0, oacc[nt][1] - lse0);
        *(float2*)(out + (size_t)row_hi * OD + col) =
            make_float2(oacc[nt][2] - lse1, oacc[nt][3] - lse1);
    }
}

// ===========================================================================
// Launch. Inputs: 0:x 1:g 2:W1 3:b1 4:W2 5:b2 6:alpha 7:beta
// ===========================================================================
extern "C" void kernel_launch(void* const* d_in, const int* in_sizes, int n_in,
                              void* d_out, int out_size)
{
    (void)in_sizes; (void)n_in; (void)out_size;
    const float* x     = (const float*)d_in[0];
    const float* W1    = (const float*)d_in[2];
    const float* b1    = (const float*)d_in[3];
    const float* W2    = (const float*)d_in[4];
    const float* b2    = (const float*)d_in[5];
    const float* alpha = (const float*)d_in[6];
    const float* beta  = (const float*)d_in[7];
    float* out = (float*)d_out;

    __nv_bfloat16 *xb, *w1b, *w2b, *h1b, *hbp, *hbTp;
    float *hp;
    cudaGetSymbolAddress((void**)&xb,   g_xb);
    cudaGetSymbolAddress((void**)&w1b,  g_w1b);
    cudaGetSymbolAddress((void**)&w2b,  g_w2b);
    cudaGetSymbolAddress((void**)&h1b,  g_h1b);
    cudaGetSymbolAddress((void**)&hp,   g_h);
    cudaGetSymbolAddress((void**)&hbp,  g_hb);
    cudaGetSymbolAddress((void**)&hbTp, g_hbT);

    cvt_bf16_kernel<<<(NROWS * IND / 4 + 255) / 256, 256>>>(x,  xb,  NROWS * IND / 4);
    cvt_bf16_kernel<<<(IND * HIDD / 4 + 255) / 256, 256>>>(W1, w1b, IND * HIDD / 4);
    cvt_bf16_kernel<<<(HIDD * OD / 4 + 255) / 256, 256>>>(W2, w2b, HIDD * OD / 4);

    cudaFuncSetAttribute(hgemm_kernel<IND, HIDD, true, false>,
                         cudaFuncAttributeMaxDynamicSharedMemorySize, GEMM_SMEM);
    hgemm_kernel<IND, HIDD, true, false>
        <<<dim3(HIDD / 128, NROWS / 128), 256, GEMM_SMEM>>>(
            xb, w1b, b1, nullptr, h1b);

    cudaFuncSetAttribute(hgemm_kernel<HIDD, OD, false, true>,
                         cudaFuncAttributeMaxDynamicSharedMemorySize, GEMM_SMEM);
    hgemm_kernel<HIDD, OD, false, true>
        <<<dim3(OD / 128, NROWS / 128), 256, GEMM_SMEM>>>(
            h1b, w2b, b2, hp, hbp);

    transpose_kernel<<<NROWS / 64, 256>>>(hbp, hbTp);

    cudaFuncSetAttribute(flash_hmma_kernel,
                         cudaFuncAttributeMaxDynamicSharedMemorySize, FLASH_SMEM);
    flash_hmma_kernel<<<NROWS / 128, 256, FLASH_SMEM>>>(hbp, hbTp, hp,
                                                        alpha, beta, out);
}

// round 10
// speedup vs baseline: 1.2506x; 1.2506x over previous
#include <cuda_runtime.h>
#include <cuda_bf16.h>
#include <cstdint>
#include <math.h>

// Problem dims (fixed per reference)
#define NROWS 16384
#define IND   512
#define HIDD  256
#define OD    128
#define NB    (NROWS / 128)

// Scratch (device globals; no allocations allowed)
__device__ __nv_bfloat16 g_xb [NROWS * IND];    // bf16 x
__device__ __nv_bfloat16 g_w1b[IND * HIDD];     // bf16 W1
__device__ __nv_bfloat16 g_w2b[HIDD * OD];      // bf16 W2
__device__ __nv_bfloat16 g_h1b[NROWS * HIDD];   // bf16 h1 (after leaky)
__device__ float         g_h  [NROWS * OD];     // fp32 h (epilogue)
// bf16 h in SWIZZLED BLOCK layout: 128 blocks of 32KB; within block
// (r, byte b): off = r*256 + (((b>>4) ^ (r&7))<<4) + (b&15)
__device__ __nv_bfloat16 g_hb [NROWS * OD];

// ===========================================================================
// PTX helpers
// ===========================================================================
__device__ __forceinline__ uint32_t smem_to_u32(const void* p) {
    uint32_t a;
    asm("{ .reg .u64 t; cvta.to.shared.u64 t, %1; cvt.u32.u64 %0, t; }"
        : "=r"(a) : "l"(p));
    return a;
}

__device__ __forceinline__ void cp_async16(uint32_t dst, const void* src) {
    asm volatile("cp.async.cg.shared.global [%0], [%1], 16;"
                 :: "r"(dst), "l"(src));
}
#define CP_COMMIT asm volatile("cp.async.commit_group;" ::: "memory")
#define CP_WAIT0  asm volatile("cp.async.wait_group 0;" ::: "memory")

// 1D bulk copy global->shared with mbarrier completion (sm_90 base)
__device__ __forceinline__ void bulk_cp(uint32_t dst, const void* src,
                                        uint32_t bytes, uint32_t mbar) {
    asm volatile(
        "cp.async.bulk.shared::cluster.global.mbarrier::complete_tx::bytes "
        "[%0], [%1], %2, [%3];"
        :: "r"(dst), "l"(src), "r"(bytes), "r"(mbar) : "memory");
}

#define MBARRIER_INIT(mbar, cnt) \
    asm volatile("mbarrier.init.shared.b64 [%0], %1;" \
        :: "r"((uint32_t)(mbar)), "r"((uint32_t)(cnt)) : "memory")
#define MBARRIER_EXPECT_TX(mbar, tx) \
    asm volatile("mbarrier.arrive.expect_tx.shared.b64 _, [%0], %1;" \
        :: "r"((uint32_t)(mbar)), "r"((uint32_t)(tx)) : "memory")
#define MBARRIER_WAIT_PARITY(mbar, parity) do {                                   \
    uint32_t _m = (uint32_t)(mbar);                                               \
    uint32_t _p = (uint32_t)(parity);                                             \
    uint32_t _done;                                                               \
    asm volatile(                                                                 \
        "{\n\t.reg .pred p;\n\t"                                                  \
        "mbarrier.try_wait.parity.acquire.cta.shared::cta.b64 p, [%1], %2;\n\t"   \
        "selp.b32 %0, 1, 0, p;\n\t}"                                              \
        : "=r"(_done) : "r"(_m), "r"(_p) : "memory");                             \
    if (!_done) {                                                                 \
        asm volatile(                                                             \
            "{\n\t.reg .pred P1;\n\t"                                             \
            "WAIT_LOOP_%=:\n\t"                                                   \
            "mbarrier.try_wait.parity.acquire.cta.shared::cta.b64 P1, [%0], %1, 0x989680;\n\t" \
            "@P1 bra.uni WAIT_DONE_%=;\n\t"                                       \
            "bra.uni WAIT_LOOP_%=;\n\t"                                           \
            "WAIT_DONE_%=:\n\t}"                                                  \
            :: "r"(_m), "r"(_p) : "memory");                                      \
    }                                                                             \
} while (0)

__device__ __forceinline__ void ldsm_x4(uint32_t* r, uint32_t addr) {
    asm volatile("ldmatrix.sync.aligned.m8n8.x4.shared.b16 {%0,%1,%2,%3}, [%4];"
                 : "=r"(r[0]), "=r"(r[1]), "=r"(r[2]), "=r"(r[3]) : "r"(addr));
}
__device__ __forceinline__ void ldsm_x4_t(uint32_t* r, uint32_t addr) {
    asm volatile("ldmatrix.sync.aligned.m8n8.x4.trans.shared.b16 {%0,%1,%2,%3}, [%4];"
                 : "=r"(r[0]), "=r"(r[1]), "=r"(r[2]), "=r"(r[3]) : "r"(addr));
}
__device__ __forceinline__ uint32_t movm(uint32_t a) {
    uint32_t d;
    asm("movmatrix.sync.aligned.m8n8.trans.b16 %0, %1;" : "=r"(d) : "r"(a));
    return d;
}

__device__ __forceinline__ void mma16816(float* c, const uint32_t* a,
                                         const uint32_t b0, const uint32_t b1) {
    asm volatile(
        "mma.sync.aligned.m16n8k16.row.col.f32.bf16.bf16.f32 "
        "{%0,%1,%2,%3}, {%4,%5,%6,%7}, {%8,%9}, {%0,%1,%2,%3};"
        : "+f"(c[0]), "+f"(c[1]), "+f"(c[2]), "+f"(c[3])
        : "r"(a[0]), "r"(a[1]), "r"(a[2]), "r"(a[3]), "r"(b0), "r"(b1));
}

__device__ __forceinline__ uint32_t pack_bf16x2(float hi, float lo) {
    uint32_t d;
    asm("cvt.rn.bf16x2.f32 %0, %1, %2;" : "=r"(d) : "f"(hi), "f"(lo));
    return d;
}
__device__ __forceinline__ uint32_t hmul2(uint32_t a, uint32_t b) {
    uint32_t d;
    asm("mul.rn.bf16x2 %0, %1, %2;" : "=r"(d) : "r"(a), "r"(b));
    return d;
}
__device__ __forceinline__ float ex2f(float x) {
    float d;
    asm("ex2.approx.f32 %0, %1;" : "=f"(d) : "f"(x));
    return d;
}
#define L2E_BF16X2 0x3FB93FB9u   // bf16x2 {log2(e), log2(e)}

// ===========================================================================
// fp32 -> bf16 conversion (vectorized x4)
// ===========================================================================
__global__ __launch_bounds__(256) void cvt_bf16_kernel(
    const float* __restrict__ in, __nv_bfloat16* __restrict__ out, int n4)
{
    int i = blockIdx.x * 256 + threadIdx.x;
    if (i < n4) {
        float4 v = ((const float4*)in)[i];
        ((uint2*)out)[i] = make_uint2(pack_bf16x2(v.y, v.x),
                                      pack_bf16x2(v.w, v.z));
    }
}

// ===========================================================================
// bf16 HMMA GEMM: C = A(bf16)@B(bf16) + bias, optional LeakyReLU.
// SWZ_CB: write Cb in the swizzled 128-row-block layout for flash.
// ===========================================================================
#define GA_STRIDE 144
#define GA_BUF    (128 * GA_STRIDE)
#define GB_STRIDE 272
#define GB_BUF    (64 * GB_STRIDE)
#define GEMM_SMEM (2 * GA_BUF + 2 * GB_BUF)

template<int KDIM, int NGLOB, bool LEAKY, bool WRITE_F32, bool SWZ_CB>
__global__ __launch_bounds__(256, 2) void hgemm_kernel(
    const __nv_bfloat16* __restrict__ A, const __nv_bfloat16* __restrict__ B,
    const float* __restrict__ bias, float* __restrict__ C,
    __nv_bfloat16* __restrict__ Cb)
{
    extern __shared__ char smem[];
    const uint32_t sb = smem_to_u32(smem);
    const int tid = threadIdx.x;
    const int wid = tid >> 5, lane = tid & 31;
    const int m0 = blockIdx.y * 128, n0 = blockIdx.x * 128;

    const uint32_t sA[2] = { sb, sb + GA_BUF };
    const uint32_t sB[2] = { sb + 2 * GA_BUF, sb + 2 * GA_BUF + GB_BUF };

    float acc[16][4];
    #pragma unroll
    for (int i = 0; i < 16; i++)
        #pragma unroll
        for (int j = 0; j < 4; j++) acc[i][j] = 0.f;

    const int brow  = lane & 15;
    const int bcolb = ((lane >> 4) << 3) * 2;
    const int vrow  = ((lane >> 4) << 3) + (lane & 7);
    const int vcolb = (((lane >> 3) & 1) << 3) * 2;

    auto fill = [&](int bi, int k0) {
        #pragma unroll
        for (int it = 0; it < 4; it++) {
            int c = it * 256 + tid;
            int r = c >> 3, c8 = c & 7;
            cp_async16(sA[bi] + r * GA_STRIDE + c8 * 16,
                       A + (size_t)(m0 + r) * KDIM + k0 + c8 * 8);
        }
        #pragma unroll
        for (int it = 0; it < 4; it++) {
            int c = it * 256 + tid;
            int r = c >> 4, cc = c & 15;
            cp_async16(sB[bi] + r * GB_STRIDE + cc * 16,
                       B + (size_t)(k0 + r) * NGLOB + n0 + cc * 8);
        }
        CP_COMMIT;
    };

    fill(0, 0);
    constexpr int NC = KDIM / 64;

    for (int ck = 0; ck < NC; ck++) {
        CP_WAIT0;
        __syncthreads();
        if (ck + 1 < NC) fill((ck + 1) & 1, (ck + 1) * 64);

        const uint32_t cA = sA[ck & 1], cB = sB[ck & 1];

        uint32_t af[4][4];
        const uint32_t ab = cA + (wid * 16 + brow) * GA_STRIDE + bcolb;
        #pragma unroll
        for (int kt = 0; kt < 4; kt++) ldsm_x4(af[kt], ab + kt * 32);

        #pragma unroll
        for (int kt = 0; kt < 4; kt++) {
            const uint32_t rb = cB + (kt * 16 + vrow) * GB_STRIDE + vcolb;
            #pragma unroll
            for (int jp = 0; jp < 8; jp++) {
                uint32_t r[4];
                ldsm_x4_t(r, rb + jp * 32);
                mma16816(acc[2 * jp],     af[kt], r[0], r[2]);
                mma16816(acc[2 * jp + 1], af[kt], r[1], r[3]);
            }
        }
    }

    const int g = lane >> 2, t = lane & 3;
    const int row_lo = m0 + wid * 16 + g;
    const int row_hi = row_lo + 8;
    #pragma unroll
    for (int nt = 0; nt < 16; nt++) {
        const int col = n0 + nt * 8 + 2 * t;
        const float bb0 = bias[col], bb1 = bias[col + 1];
        float v0 = acc[nt][0] + bb0, v1 = acc[nt][1] + bb1;
        float v2 = acc[nt][2] + bb0, v3 = acc[nt][3] + bb1;
        if (LEAKY) {
            v0 = v0 >= 0.f ? v0 : 0.01f * v0;
            v1 = v1 >= 0.f ? v1 : 0.01f * v1;
            v2 = v2 >= 0.f ? v2 : 0.01f * v2;
            v3 = v3 >= 0.f ? v3 : 0.01f * v3;
        }
        if (WRITE_F32) {
            *(float2*)(C + (size_t)row_lo * NGLOB + col) = make_float2(v0, v1);
            *(float2*)(C + (size_t)row_hi * NGLOB + col) = make_float2(v2, v3);
        }
        if (SWZ_CB) {
            // swizzled block layout (NGLOB==128 path)
            const uint32_t chunk = (uint32_t)(col >> 3);
            const uint32_t inb   = (uint32_t)((col * 2) & 15);
            const uint32_t off_lo = ((uint32_t)(row_lo >> 7)) * 32768u
                + (uint32_t)(row_lo & 127) * 256u
                + (((chunk ^ (uint32_t)(row_lo & 7)) << 4) | inb);
            const uint32_t off_hi = ((uint32_t)(row_hi >> 7)) * 32768u
                + (uint32_t)(row_hi & 127) * 256u
                + (((chunk ^ (uint32_t)(row_hi & 7)) << 4) | inb);
            *(uint32_t*)((char*)Cb + off_lo) = pack_bf16x2(v1, v0);
            *(uint32_t*)((char*)Cb + off_hi) = pack_bf16x2(v3, v2);
        } else {
            *(uint32_t*)(Cb + (size_t)row_lo * NGLOB + col) = pack_bf16x2(v1, v0);
            *(uint32_t*)(Cb + (size_t)row_hi * NGLOB + col) = pack_bf16x2(v3, v2);
        }
    }
}

// ===========================================================================
// HMMA flash similarity kernel (R10):
//   R4 inner loop (movm PV path, proven fastest), but tiles arrive via ONE
//   cp.async.bulk per 32KB block (mbarrier completion) instead of 2048
//   per-thread cp.asyncs — removes ~4096 LDGSTS cyc/SMSP/iter, the co-binder.
//   Tiles live in a swizzled block layout (conflict-free ldsm).
//   Q frags pre-scaled by log2(e); exp via ex2.approx.
// ===========================================================================
#define TILE_B 32768
#define FLASH_SMEM (2 * TILE_B + 64)   // 65600

__global__ __launch_bounds__(256, 1)
void flash_hmma_kernel(const __nv_bfloat16* __restrict__ hbs,  // swizzled
                       const float* __restrict__ h,
                       const float* __restrict__ alpha,
                       const float* __restrict__ beta,
                       float* __restrict__ out)
{
    extern __shared__ char smem[];
    const uint32_t sbase = smem_to_u32(smem);
    const uint32_t mQ = sbase + 2 * TILE_B;
    const uint32_t mb0 = mQ + 8, mb1 = mQ + 16;
    const int tid = threadIdx.x;
    const int wid = tid >> 5, lane = tid & 31;
    const int r0 = blockIdx.x * 128;
    const char* hbase = (const char*)hbs;

    if (tid == 0) {
        MBARRIER_INIT(mQ, 1);
        MBARRIER_INIT(mb0, 1);
        MBARRIER_INIT(mb1, 1);
    }
    __syncthreads();

    // Kick Q tile bulk copy into buf0
    if (tid == 0) {
        MBARRIER_EXPECT_TX(mQ, TILE_B);
        bulk_cp(sbase, hbase + (size_t)blockIdx.x * TILE_B, TILE_B, mQ);
    }

    // per-thread swizzled chunk offsets (constant across nbk/kb)
    const int brow = lane & 15;
    const int hc = lane >> 4;        // 0/1: which 16B chunk half
    const int xr = lane & 7;
    uint32_t choff[8];
    #pragma unroll
    for (int dk = 0; dk < 8; dk++)
        choff[dk] = (uint32_t)(((dk * 2 + hc) ^ xr) << 4);

    MBARRIER_WAIT_PARITY(mQ, 0);

    uint32_t qf[8][4];
    {
        const uint32_t qb = sbase + (uint32_t)(wid * 16 + brow) * 256u;
        #pragma unroll
        for (int kt = 0; kt < 8; kt++) {
            ldsm_x4(qf[kt], qb + choff[kt]);
            #pragma unroll
            for (int i = 0; i < 4; i++)
                qf[kt][i] = hmul2(qf[kt][i], L2E_BF16X2);  // fold log2(e)
        }
    }
    __syncthreads();   // all threads done reading Q from buf0

    // Kick key-block 0 into buf0
    if (tid == 0) {
        MBARRIER_EXPECT_TX(mb0, TILE_B);
        bulk_cp(sbase, hbase, TILE_B, mb0);
    }

    float oacc[16][4];
    #pragma unroll
    for (int i = 0; i < 16; i++)
        #pragma unroll
        for (int j = 0; j < 4; j++) oacc[i][j] = 0.f;
    float l0 = 0.f, l1 = 0.f;

    for (int kb = 0; kb < NB; kb++) {
        MBARRIER_WAIT_PARITY((kb & 1) ? mb1 : mb0, (kb >> 1) & 1);
        __syncthreads();   // all warps done reading the OTHER buffer (iter kb-1)
        if (tid == 0 && kb + 1 < NB) {
            const uint32_t mm = ((kb + 1) & 1) ? mb1 : mb0;
            MBARRIER_EXPECT_TX(mm, TILE_B);
            bulk_cp(sbase + (uint32_t)((kb + 1) & 1) * TILE_B,
                    hbase + (size_t)(kb + 1) * TILE_B, TILE_B, mm);
        }

        const uint32_t cur = sbase + (uint32_t)(kb & 1) * TILE_B;

        #pragma unroll
        for (int nbk = 0; nbk < 8; nbk++) {
            // K fragments (non-trans, swizzled addressing)
            uint32_t r[8][4];
            const uint32_t rb = cur + (uint32_t)(nbk * 16 + brow) * 256u;
            #pragma unroll
            for (int dk = 0; dk < 8; dk++) ldsm_x4(r[dk], rb + choff[dk]);

            // S' = (Q*log2e) @ K^T for this n-block
            float s0[4] = {0.f, 0.f, 0.f, 0.f};
            float s1[4] = {0.f, 0.f, 0.f, 0.f};
            #pragma unroll
            for (int dk = 0; dk < 8; dk++) {
                mma16816(s0, qf[dk], r[dk][0], r[dk][2]);
                mma16816(s1, qf[dk], r[dk][1], r[dk][3]);
            }

            // masked exp: p = (s'>0) ? 2^{s'} : 0 (sign test scale-invariant)
            float p00 = s0[0] > 0.f ? ex2f(s0[0]) : 0.f;
            float p01 = s0[1] > 0.f ? ex2f(s0[1]) : 0.f;
            float p02 = s0[2] > 0.f ? ex2f(s0[2]) : 0.f;
            float p03 = s0[3] > 0.f ? ex2f(s0[3]) : 0.f;
            float p10 = s1[0] > 0.f ? ex2f(s1[0]) : 0.f;
            float p11 = s1[1] > 0.f ? ex2f(s1[1]) : 0.f;
            float p12 = s1[2] > 0.f ? ex2f(s1[2]) : 0.f;
            float p13 = s1[3] > 0.f ? ex2f(s1[3]) : 0.f;
            l0 += (p00 + p01) + (p10 + p11);
            l1 += (p02 + p03) + (p12 + p13);
            uint32_t af[4] = { pack_bf16x2(p01, p00), pack_bf16x2(p03, p02),
                               pack_bf16x2(p11, p10), pack_bf16x2(p13, p12) };

            // O += P @ V ; B-frags via in-register transpose (R4 path)
            #pragma unroll
            for (int dk = 0; dk < 8; dk++) {
                mma16816(oacc[2 * dk],     af, movm(r[dk][0]), movm(r[dk][1]));
                mma16816(oacc[2 * dk + 1], af, movm(r[dk][2]), movm(r[dk][3]));
            }
        }
    }

    // ---- reduce row sums across the quad ----
    l0 += __shfl_xor_sync(0xffffffffu, l0, 1);
    l0 += __shfl_xor_sync(0xffffffffu, l0, 2);
    l1 += __shfl_xor_sync(0xffffffffu, l1, 1);
    l1 += __shfl_xor_sync(0xffffffffu, l1, 2);

    // ---- epilogue: v = alpha*O/l + beta*h, then log_softmax per row ----
    const float a_ = alpha[0], b_ = beta[0];
    const float s0_ = a_ / l0, s1_ = a_ / l1;
    const int g = lane >> 2, t = lane & 3;
    const int row_lo = r0 + wid * 16 + g;
    const int row_hi = row_lo + 8;

    float mx0 = -INFINITY, mx1 = -INFINITY;
    #pragma unroll
    for (int nt = 0; nt < 16; nt++) {
        const int col = nt * 8 + 2 * t;
        float2 hlo = *(const float2*)(h + (size_t)row_lo * OD + col);
        float2 hhi = *(const float2*)(h + (size_t)row_hi * OD + col);
        float v0 = s0_ * oacc[nt][0] + b_ * hlo.x;
        float v1 = s0_ * oacc[nt][1] + b_ * hlo.y;
        float v2 = s1_ * oacc[nt][2] + b_ * hhi.x;
        float v3 = s1_ * oacc[nt][3] + b_ * hhi.y;
        oacc[nt][0] = v0; oacc[nt][1] = v1;
        oacc[nt][2] = v2; oacc[nt][3] = v3;
        mx0 = fmaxf(mx0, fmaxf(v0, v1));
        mx1 = fmaxf(mx1, fmaxf(v2, v3));
    }
    mx0 = fmaxf(mx0, __shfl_xor_sync(0xffffffffu, mx0, 1));
    mx0 = fmaxf(mx0, __shfl_xor_sync(0xffffffffu, mx0, 2));
    mx1 = fmaxf(mx1, __shfl_xor_sync(0xffffffffu, mx1, 1));
    mx1 = fmaxf(mx1, __shfl_xor_sync(0xffffffffu, mx1, 2));

    float se0 = 0.f, se1 = 0.f;
    #pragma unroll
    for (int nt = 0; nt < 16; nt++) {
        se0 += __expf(oacc[nt][0] - mx0) + __expf(oacc[nt][1] - mx0);
        se1 += __expf(oacc[nt][2] - mx1) + __expf(oacc[nt][3] - mx1);
    }
    se0 += __shfl_xor_sync(0xffffffffu, se0, 1);
    se0 += __shfl_xor_sync(0xffffffffu, se0, 2);
    se1 += __shfl_xor_sync(0xffffffffu, se1, 1);
    se1 += __shfl_xor_sync(0xffffffffu, se1, 2);
    const float lse0 = mx0 + logf(se0);
    const float lse1 = mx1 + logf(se1);

    #pragma unroll
    for (int nt = 0; nt < 16; nt++) {
        const int col = nt * 8 + 2 * t;
        *(float2*)(out + (size_t)row_lo * OD + col) =
            make_float2(oacc[nt][0] - lse0, oacc[nt][1] - lse0);
        *(float2*)(out + (size_t)row_hi * OD + col) =
            make_float2(oacc[nt][2] - lse1, oacc[nt][3] - lse1);
    }
}

// ===========================================================================
// Launch. Inputs: 0:x 1:g 2:W1 3:b1 4:W2 5:b2 6:alpha 7:beta
// ===========================================================================
extern "C" void kernel_launch(void* const* d_in, const int* in_sizes, int n_in,
                              void* d_out, int out_size)
{
    (void)in_sizes; (void)n_in; (void)out_size;
    const float* x     = (const float*)d_in[0];
    const float* W1    = (const float*)d_in[2];
    const float* b1    = (const float*)d_in[3];
    const float* W2    = (const float*)d_in[4];
    const float* b2    = (const float*)d_in[5];
    const float* alpha = (const float*)d_in[6];
    const float* beta  = (const float*)d_in[7];
    float* out = (float*)d_out;

    __nv_bfloat16 *xb, *w1b, *w2b, *h1b, *hbp;
    float *hp;
    cudaGetSymbolAddress((void**)&xb,  g_xb);
    cudaGetSymbolAddress((void**)&w1b, g_w1b);
    cudaGetSymbolAddress((void**)&w2b, g_w2b);
    cudaGetSymbolAddress((void**)&h1b, g_h1b);
    cudaGetSymbolAddress((void**)&hp,  g_h);
    cudaGetSymbolAddress((void**)&hbp, g_hb);

    cvt_bf16_kernel<<<(NROWS * IND / 4 + 255) / 256, 256>>>(x,  xb,  NROWS * IND / 4);
    cvt_bf16_kernel<<<(IND * HIDD / 4 + 255) / 256, 256>>>(W1, w1b, IND * HIDD / 4);
    cvt_bf16_kernel<<<(HIDD * OD / 4 + 255) / 256, 256>>>(W2, w2b, HIDD * OD / 4);

    cudaFuncSetAttribute(hgemm_kernel<IND, HIDD, true, false, false>,
                         cudaFuncAttributeMaxDynamicSharedMemorySize, GEMM_SMEM);
    hgemm_kernel<IND, HIDD, true, false, false>
        <<<dim3(HIDD / 128, NROWS / 128), 256, GEMM_SMEM>>>(
            xb, w1b, b1, nullptr, h1b);

    cudaFuncSetAttribute(hgemm_kernel<HIDD, OD, false, true, true>,
                         cudaFuncAttributeMaxDynamicSharedMemorySize, GEMM_SMEM);
    hgemm_kernel<HIDD, OD, false, true, true>
        <<<dim3(OD / 128, NROWS / 128), 256, GEMM_SMEM>>>(
            h1b, w2b, b2, hp, hbp);

    cudaFuncSetAttribute(flash_hmma_kernel,
                         cudaFuncAttributeMaxDynamicSharedMemorySize, FLASH_SMEM);
    flash_hmma_kernel<<<NROWS / 128, 256, FLASH_SMEM>>>(hbp, hp, alpha, beta, out);
}